// round 5
// baseline (speedup 1.0000x reference)
#include <cuda_runtime.h>
#include <math.h>

#define N_NODES 100000
#define NE      1600000
#define NG      512
#define DH      128
#define BN_EPS  1e-5f

// ---------------- device scratch (no allocation allowed) ----------------
__device__ int   g_cnt     [N_NODES];
__device__ int   g_rowstart[N_NODES + 1];
__device__ int   g_cursor  [N_NODES];
__device__ int   g_csrc    [NE];
__device__ float g_dinv    [N_NODES];
__device__ float g_HS      [(size_t)N_NODES * DH];
__device__ float g_XA      [(size_t)N_NODES * DH];
__device__ float g_XB      [(size_t)N_NODES * DH];
__device__ float g_pool    [NG * 2 * DH];
__device__ int   g_gstart  [NG + 1];

// ---------------- helpers ----------------
__device__ __forceinline__ unsigned long long pack2(float f) {
    unsigned long long r;
    unsigned u = __float_as_uint(f);
    asm("mov.b64 %0, {%1, %1};" : "=l"(r) : "r"(u));
    return r;
}
__device__ __forceinline__ void ffma2(unsigned long long& d,
                                      unsigned long long a,
                                      unsigned long long b) {
    asm("fma.rn.f32x2 %0, %1, %2, %0;" : "+l"(d) : "l"(a), "l"(b));
}

// ---------------- degree / dinv ----------------
__global__ void k_cnt_zero(int* cnt) {
    int i = blockIdx.x * blockDim.x + threadIdx.x;
    if (i < N_NODES) cnt[i] = 0;
}
__global__ void k_deg_count(const int* __restrict__ dst, int* cnt) {
    int e = blockIdx.x * blockDim.x + threadIdx.x;
    if (e < NE) atomicAdd(&cnt[dst[e]], 1);
}
__global__ void k_dinv(const int* __restrict__ cnt, float* __restrict__ dinv) {
    int i = blockIdx.x * blockDim.x + threadIdx.x;
    if (i < N_NODES) dinv[i] = rsqrtf((float)(cnt[i] + 1));  // +1 self-loop
}

// ---------------- prefix scan over counts (single block) ----------------
#define SCAN_T 1024
#define SCAN_CH 98   // 1024*98 = 100352 >= N_NODES
__global__ __launch_bounds__(SCAN_T)
void k_scan(const int* __restrict__ cnt, int* __restrict__ rowstart,
            int* __restrict__ cursor)
{
    __shared__ int sums[SCAN_T];
    int t = threadIdx.x;
    int lo = t * SCAN_CH;
    int hi = lo + SCAN_CH; if (hi > N_NODES) hi = N_NODES;
    int s = 0;
    for (int i = lo; i < hi; i++) s += cnt[i];
    sums[t] = s;
    __syncthreads();
    // Hillis-Steele inclusive scan
    for (int off = 1; off < SCAN_T; off <<= 1) {
        int v = (t >= off) ? sums[t - off] : 0;
        __syncthreads();
        sums[t] += v;
        __syncthreads();
    }
    int run = sums[t] - s;   // exclusive base
    for (int i = lo; i < hi; i++) {
        rowstart[i] = run;
        cursor[i]   = run;
        run += cnt[i];
    }
    if (t == SCAN_T - 1) rowstart[N_NODES] = run;   // == NE
}

// ---------------- CSR fill ----------------
__global__ void k_fill(const int* __restrict__ src,
                       const int* __restrict__ dst,
                       int* __restrict__ cursor, int* __restrict__ csrc)
{
    int e = blockIdx.x * blockDim.x + threadIdx.x;
    if (e >= NE) return;
    int d = dst[e];
    int pos = atomicAdd(&cursor[d], 1);
    csrc[pos] = src[e];
}

// ---------------- GEMM: HS = (X @ W) * dinv[row] ----------------
#define TR 64
__global__ __launch_bounds__(256)
void k_gemm(const float* __restrict__ X, const float* __restrict__ W,
            const float* __restrict__ dinv, float* __restrict__ HS, int n)
{
    extern __shared__ float sm[];
    float* Wsm = sm;            // 128*128
    float* XT  = sm + DH * DH;  // [k][r], row length TR
    int tid = threadIdx.x;
    int row0 = blockIdx.x * TR;

    {
        const float4* w4 = (const float4*)W;
        float4* s4 = (float4*)Wsm;
        for (int i = tid; i < DH * DH / 4; i += 256) s4[i] = w4[i];
    }
    {
        int r  = tid >> 2;
        int kq = tid & 3;
        int grow = row0 + r;
        #pragma unroll
        for (int kb = 0; kb < 8; kb++) {
            int k = kb * 16 + kq * 4;
            float4 v = make_float4(0.f, 0.f, 0.f, 0.f);
            if (grow < n) v = *(const float4*)(X + (size_t)grow * DH + k);
            XT[(k + 0) * TR + r] = v.x;
            XT[(k + 1) * TR + r] = v.y;
            XT[(k + 2) * TR + r] = v.z;
            XT[(k + 3) * TR + r] = v.w;
        }
    }
    __syncthreads();

    int ct = tid & 31;
    int rt = tid >> 5;
    int c0 = ct * 4, r0 = rt * 8;

    unsigned long long acc[4][4];
    #pragma unroll
    for (int a = 0; a < 4; a++)
        #pragma unroll
        for (int b = 0; b < 4; b++) acc[a][b] = 0ULL;

    #pragma unroll 4
    for (int k = 0; k < DH; k++) {
        const unsigned long long* xr =
            (const unsigned long long*)(XT + k * TR + r0);
        unsigned long long xp0 = xr[0], xp1 = xr[1], xp2 = xr[2], xp3 = xr[3];
        float4 w = *(const float4*)(Wsm + k * DH + c0);
        unsigned long long wp0 = pack2(w.x), wp1 = pack2(w.y),
                           wp2 = pack2(w.z), wp3 = pack2(w.w);
        ffma2(acc[0][0], xp0, wp0); ffma2(acc[0][1], xp0, wp1);
        ffma2(acc[0][2], xp0, wp2); ffma2(acc[0][3], xp0, wp3);
        ffma2(acc[1][0], xp1, wp0); ffma2(acc[1][1], xp1, wp1);
        ffma2(acc[1][2], xp1, wp2); ffma2(acc[1][3], xp1, wp3);
        ffma2(acc[2][0], xp2, wp0); ffma2(acc[2][1], xp2, wp1);
        ffma2(acc[2][2], xp2, wp2); ffma2(acc[2][3], xp2, wp3);
        ffma2(acc[3][0], xp3, wp0); ffma2(acc[3][1], xp3, wp1);
        ffma2(acc[3][2], xp3, wp2); ffma2(acc[3][3], xp3, wp3);
    }

    #pragma unroll
    for (int rp = 0; rp < 4; rp++) {
        int r_even = row0 + r0 + 2 * rp;
        int r_odd  = r_even + 1;
        if (r_even < n) {
            float dv = dinv[r_even];
            float4 o;
            o.x = __uint_as_float((unsigned)(acc[rp][0])) * dv;
            o.y = __uint_as_float((unsigned)(acc[rp][1])) * dv;
            o.z = __uint_as_float((unsigned)(acc[rp][2])) * dv;
            o.w = __uint_as_float((unsigned)(acc[rp][3])) * dv;
            *(float4*)(HS + (size_t)r_even * DH + c0) = o;
        }
        if (r_odd < n) {
            float dv = dinv[r_odd];
            float4 o;
            o.x = __uint_as_float((unsigned)(acc[rp][0] >> 32)) * dv;
            o.y = __uint_as_float((unsigned)(acc[rp][1] >> 32)) * dv;
            o.z = __uint_as_float((unsigned)(acc[rp][2] >> 32)) * dv;
            o.w = __uint_as_float((unsigned)(acc[rp][3] >> 32)) * dv;
            *(float4*)(HS + (size_t)r_odd * DH + c0) = o;
        }
    }
}

// ------- gather + self-loop + dinv + BN + ReLU + residual (fused) -------
// warp per node; lane handles columns [lane*4, lane*4+4)
__global__ __launch_bounds__(256)
void k_gather(const float* __restrict__ HS,
              const int* __restrict__ rowstart, const int* __restrict__ csrc,
              const float* __restrict__ dinv, const float* __restrict__ prev,
              float* __restrict__ Xout,
              const float* __restrict__ cb, const float* __restrict__ gg,
              const float* __restrict__ bt, const float* __restrict__ mm,
              const float* __restrict__ vv)
{
    int warp = (blockIdx.x * blockDim.x + threadIdx.x) >> 5;
    int lane = threadIdx.x & 31;
    if (warp >= N_NODES) return;
    int i = warp;
    int c = lane * 4;

    int s0 = rowstart[i], s1 = rowstart[i + 1];

    // self-loop contribution
    float4 acc = *(const float4*)(HS + (size_t)i * DH + c);

    for (int jb = s0; jb < s1; jb += 32) {
        int idx = 0;
        if (jb + lane < s1) idx = csrc[jb + lane];        // coalesced batch
        int cnt = s1 - jb; if (cnt > 32) cnt = 32;
        for (int q = 0; q < cnt; q++) {
            int s = __shfl_sync(0xffffffffu, idx, q);
            float4 h = *(const float4*)(HS + (size_t)s * DH + c);
            acc.x += h.x; acc.y += h.y; acc.z += h.z; acc.w += h.w;
        }
    }

    float dv = dinv[i];
    float4 cb4 = *(const float4*)(cb + c);
    float4 g4  = *(const float4*)(gg + c);
    float4 bt4 = *(const float4*)(bt + c);
    float4 m4  = *(const float4*)(mm + c);
    float4 v4  = *(const float4*)(vv + c);
    float4 o;
    o.x = fmaxf((acc.x * dv + cb4.x - m4.x) * (g4.x * rsqrtf(v4.x + BN_EPS)) + bt4.x, 0.f);
    o.y = fmaxf((acc.y * dv + cb4.y - m4.y) * (g4.y * rsqrtf(v4.y + BN_EPS)) + bt4.y, 0.f);
    o.z = fmaxf((acc.z * dv + cb4.z - m4.z) * (g4.z * rsqrtf(v4.z + BN_EPS)) + bt4.z, 0.f);
    o.w = fmaxf((acc.w * dv + cb4.w - m4.w) * (g4.w * rsqrtf(v4.w + BN_EPS)) + bt4.w, 0.f);
    if (prev) {
        float4 p = *(const float4*)(prev + (size_t)i * DH + c);
        o.x += p.x; o.y += p.y; o.z += p.z; o.w += p.w;
    }
    *(float4*)(Xout + (size_t)i * DH + c) = o;
}

// ---------------- pooling bounds from sorted batch ----------------
__global__ void k_bounds(const int* __restrict__ batch) {
    int i = blockIdx.x * blockDim.x + threadIdx.x;
    if (i >= N_NODES) return;
    int b = batch[i];
    if (i == 0) {
        for (int q = 0; q <= b; q++) g_gstart[q] = 0;
    } else {
        int pb = batch[i - 1];
        if (b != pb)
            for (int q = pb + 1; q <= b; q++) g_gstart[q] = i;
    }
    if (i == N_NODES - 1)
        for (int q = b + 1; q <= NG; q++) g_gstart[q] = N_NODES;
}

// ---------------- mean+max pooling: one block per graph ----------------
__global__ __launch_bounds__(128)
void k_pool(const float* __restrict__ X) {
    int g = blockIdx.x;
    int c = threadIdx.x;
    int s = g_gstart[g], e = g_gstart[g + 1];
    float sum = 0.f, mx = -INFINITY;
    for (int i = s; i < e; i++) {
        float t = X[(size_t)i * DH + c];
        sum += t;
        mx = fmaxf(mx, t);
    }
    float cnt = (float)(e - s);
    g_pool[g * 2 * DH + c]      = sum / cnt;
    g_pool[g * 2 * DH + DH + c] = mx;
}

// ---------------- MLP head: one block per graph ----------------
__global__ __launch_bounds__(128)
void k_mlp(const float* __restrict__ L1w, const float* __restrict__ L1b,
           const float* __restrict__ L2w, const float* __restrict__ L2b,
           const float* __restrict__ L3w, const float* __restrict__ L3b,
           float* __restrict__ out)
{
    __shared__ float h0[256], h1[128], h2[64];
    int g = blockIdx.x, t = threadIdx.x;
    h0[t]       = g_pool[g * 256 + t];
    h0[t + 128] = g_pool[g * 256 + 128 + t];
    __syncthreads();
    float a = L1b[t];
    #pragma unroll 8
    for (int k = 0; k < 256; k++) a += h0[k] * L1w[k * 128 + t];
    h1[t] = fmaxf(a, 0.f);
    __syncthreads();
    if (t < 64) {
        float b = L2b[t];
        #pragma unroll 8
        for (int k = 0; k < 128; k++) b += h1[k] * L2w[k * 64 + t];
        h2[t] = fmaxf(b, 0.f);
    }
    __syncthreads();
    if (t < 32) {
        float r = h2[t] * L3w[t] + h2[t + 32] * L3w[t + 32];
        #pragma unroll
        for (int off = 16; off; off >>= 1)
            r += __shfl_down_sync(0xffffffffu, r, off);
        if (t == 0) out[g] = r + L3b[0];
    }
}

// ---------------- launch ----------------
extern "C" void kernel_launch(void* const* d_in, const int* in_sizes, int n_in,
                              void* d_out, int out_size)
{
    const float* x    = (const float*)d_in[0];
    const int*   ei   = (const int*)d_in[1];     // int32 (JAX x64 disabled)
    const int*   batc = (const int*)d_in[2];
    const int*   src  = ei;
    const int*   dst  = ei + NE;

    const float* W[3]  = {(const float*)d_in[3],  (const float*)d_in[9],  (const float*)d_in[15]};
    const float* cb[3] = {(const float*)d_in[4],  (const float*)d_in[10], (const float*)d_in[16]};
    const float* gg[3] = {(const float*)d_in[5],  (const float*)d_in[11], (const float*)d_in[17]};
    const float* bt[3] = {(const float*)d_in[6],  (const float*)d_in[12], (const float*)d_in[18]};
    const float* mm[3] = {(const float*)d_in[7],  (const float*)d_in[13], (const float*)d_in[19]};
    const float* vv[3] = {(const float*)d_in[8],  (const float*)d_in[14], (const float*)d_in[20]};
    const float* L1w = (const float*)d_in[21];
    const float* L1b = (const float*)d_in[22];
    const float* L2w = (const float*)d_in[23];
    const float* L2b = (const float*)d_in[24];
    const float* L3w = (const float*)d_in[25];
    const float* L3b = (const float*)d_in[26];
    float* out = (float*)d_out;

    int *pCnt, *pRow, *pCur, *pCsrc;
    float *pDinv, *pHS, *pXA, *pXB;
    cudaGetSymbolAddress((void**)&pCnt,  g_cnt);
    cudaGetSymbolAddress((void**)&pRow,  g_rowstart);
    cudaGetSymbolAddress((void**)&pCur,  g_cursor);
    cudaGetSymbolAddress((void**)&pCsrc, g_csrc);
    cudaGetSymbolAddress((void**)&pDinv, g_dinv);
    cudaGetSymbolAddress((void**)&pHS,   g_HS);
    cudaGetSymbolAddress((void**)&pXA,   g_XA);
    cudaGetSymbolAddress((void**)&pXB,   g_XB);

    const int smem_gemm = (DH * DH + DH * TR) * (int)sizeof(float);  // 96KB
    cudaFuncSetAttribute(k_gemm, cudaFuncAttributeMaxDynamicSharedMemorySize, smem_gemm);

    // ---- CSR build (per launch, deterministic work) ----
    k_cnt_zero <<<(N_NODES + 255) / 256, 256>>>(pCnt);
    k_deg_count<<<(NE + 255) / 256, 256>>>(dst, pCnt);
    k_dinv     <<<(N_NODES + 255) / 256, 256>>>(pCnt, pDinv);
    k_scan     <<<1, SCAN_T>>>(pCnt, pRow, pCur);
    k_fill     <<<(NE + 255) / 256, 256>>>(src, dst, pCur, pCsrc);

    int gemm_blocks = (N_NODES + TR - 1) / TR;
    int gath_blocks = (N_NODES + 7) / 8;   // warp per node, 8 warps/block

    const float* Xin[3]  = {x,   pXA, pXB};
    const float* Prev[3] = {0,   pXA, pXB};
    float*       Xout[3] = {pXA, pXB, pXA};

    for (int L = 0; L < 3; L++) {
        k_gemm<<<gemm_blocks, 256, smem_gemm>>>(Xin[L], W[L], pDinv, pHS, N_NODES);
        k_gather<<<gath_blocks, 256>>>(pHS, pRow, pCsrc, pDinv, Prev[L], Xout[L],
                                       cb[L], gg[L], bt[L], mm[L], vv[L]);
    }

    k_bounds<<<(N_NODES + 255) / 256, 256>>>(batc);
    k_pool<<<NG, 128>>>(pXA);
    k_mlp<<<NG, 128>>>(L1w, L1b, L2w, L2b, L3w, L3b, out);
}

// round 6
// speedup vs baseline: 1.2162x; 1.2162x over previous
#include <cuda_runtime.h>
#include <math.h>

#define N_NODES 100000
#define NE      1600000
#define NG      512
#define DH      128
#define BN_EPS  1e-5f

// ---------------- device scratch (no allocation allowed) ----------------
__device__ int   g_cnt     [N_NODES];
__device__ int   g_rowstart[N_NODES + 1];
__device__ int   g_cursor  [N_NODES];
__device__ int   g_csrc    [NE];
__device__ float g_dinv    [N_NODES];
__device__ float g_HS      [(size_t)N_NODES * DH];
__device__ float g_XA      [(size_t)N_NODES * DH];
__device__ float g_XB      [(size_t)N_NODES * DH];
__device__ float g_pool    [NG * 2 * DH];
__device__ int   g_gstart  [NG + 1];
__device__ int   g_chunksum[1024];
__device__ int   g_chunkbase[1024];

// ---------------- helpers ----------------
__device__ __forceinline__ unsigned long long pack2(float f) {
    unsigned long long r;
    unsigned u = __float_as_uint(f);
    asm("mov.b64 %0, {%1, %1};" : "=l"(r) : "r"(u));
    return r;
}
__device__ __forceinline__ void ffma2(unsigned long long& d,
                                      unsigned long long a,
                                      unsigned long long b) {
    asm("fma.rn.f32x2 %0, %1, %2, %0;" : "+l"(d) : "l"(a), "l"(b));
}

// ---------------- degree / dinv ----------------
__global__ void k_cnt_zero(int* cnt) {
    int i = blockIdx.x * blockDim.x + threadIdx.x;
    if (i < N_NODES) cnt[i] = 0;
}
__global__ void k_deg_count(const int* __restrict__ dst, int* cnt) {
    int e = blockIdx.x * blockDim.x + threadIdx.x;
    if (e < NE) atomicAdd(&cnt[dst[e]], 1);
}
__global__ void k_dinv(const int* __restrict__ cnt, float* __restrict__ dinv) {
    int i = blockIdx.x * blockDim.x + threadIdx.x;
    if (i < N_NODES) dinv[i] = rsqrtf((float)(cnt[i] + 1));  // +1 self-loop
}

// ---------------- distributed 3-phase prefix scan over counts ----------------
#define NCHUNK   1024
#define CHUNK_SZ 98     // 1024*98 = 100352 >= N_NODES

// Phase 1: per-chunk sums, 1024 threads spread over 8 blocks (8 SMs)
__global__ void k_chunksum(const int* __restrict__ cnt, int* __restrict__ csum) {
    int t = blockIdx.x * blockDim.x + threadIdx.x;   // 0..1023
    int lo = t * CHUNK_SZ;
    int hi = lo + CHUNK_SZ; if (hi > N_NODES) hi = N_NODES;
    int s = 0;
    for (int i = lo; i < hi; i++) s += cnt[i];
    csum[t] = s;
}

// Phase 2: exclusive scan of the 1024 chunk sums (single block, tiny)
__global__ __launch_bounds__(NCHUNK)
void k_chunkscan(const int* __restrict__ csum, int* __restrict__ cbase) {
    __shared__ int sums[NCHUNK];
    int t = threadIdx.x;
    int v = csum[t];
    sums[t] = v;
    __syncthreads();
    for (int off = 1; off < NCHUNK; off <<= 1) {
        int u = (t >= off) ? sums[t - off] : 0;
        __syncthreads();
        sums[t] += u;
        __syncthreads();
    }
    cbase[t] = sums[t] - v;   // exclusive
}

// Phase 3: per-chunk serial write of rowstart/cursor, distributed over 8 blocks
__global__ void k_rowwrite(const int* __restrict__ cnt,
                           const int* __restrict__ cbase,
                           int* __restrict__ rowstart, int* __restrict__ cursor)
{
    int t = blockIdx.x * blockDim.x + threadIdx.x;   // 0..1023
    int lo = t * CHUNK_SZ;
    int hi = lo + CHUNK_SZ; if (hi > N_NODES) hi = N_NODES;
    int run = cbase[t];
    for (int i = lo; i < hi; i++) {
        rowstart[i] = run;
        cursor[i]   = run;
        run += cnt[i];
    }
    if (t == NCHUNK - 1) rowstart[N_NODES] = run;    // == NE
}

// ---------------- CSR fill ----------------
__global__ void k_fill(const int* __restrict__ src,
                       const int* __restrict__ dst,
                       int* __restrict__ cursor, int* __restrict__ csrc)
{
    int e = blockIdx.x * blockDim.x + threadIdx.x;
    if (e >= NE) return;
    int d = dst[e];
    int pos = atomicAdd(&cursor[d], 1);
    csrc[pos] = src[e];
}

// ---------------- GEMM: HS = (X @ W) * dinv[row] ----------------
#define TR 64
__global__ __launch_bounds__(256)
void k_gemm(const float* __restrict__ X, const float* __restrict__ W,
            const float* __restrict__ dinv, float* __restrict__ HS, int n)
{
    extern __shared__ float sm[];
    float* Wsm = sm;            // 128*128
    float* XT  = sm + DH * DH;  // [k][r], row length TR
    int tid = threadIdx.x;
    int row0 = blockIdx.x * TR;

    {
        const float4* w4 = (const float4*)W;
        float4* s4 = (float4*)Wsm;
        for (int i = tid; i < DH * DH / 4; i += 256) s4[i] = w4[i];
    }
    {
        int r  = tid >> 2;
        int kq = tid & 3;
        int grow = row0 + r;
        #pragma unroll
        for (int kb = 0; kb < 8; kb++) {
            int k = kb * 16 + kq * 4;
            float4 v = make_float4(0.f, 0.f, 0.f, 0.f);
            if (grow < n) v = *(const float4*)(X + (size_t)grow * DH + k);
            XT[(k + 0) * TR + r] = v.x;
            XT[(k + 1) * TR + r] = v.y;
            XT[(k + 2) * TR + r] = v.z;
            XT[(k + 3) * TR + r] = v.w;
        }
    }
    __syncthreads();

    int ct = tid & 31;
    int rt = tid >> 5;
    int c0 = ct * 4, r0 = rt * 8;

    unsigned long long acc[4][4];
    #pragma unroll
    for (int a = 0; a < 4; a++)
        #pragma unroll
        for (int b = 0; b < 4; b++) acc[a][b] = 0ULL;

    #pragma unroll 4
    for (int k = 0; k < DH; k++) {
        const unsigned long long* xr =
            (const unsigned long long*)(XT + k * TR + r0);
        unsigned long long xp0 = xr[0], xp1 = xr[1], xp2 = xr[2], xp3 = xr[3];
        float4 w = *(const float4*)(Wsm + k * DH + c0);
        unsigned long long wp0 = pack2(w.x), wp1 = pack2(w.y),
                           wp2 = pack2(w.z), wp3 = pack2(w.w);
        ffma2(acc[0][0], xp0, wp0); ffma2(acc[0][1], xp0, wp1);
        ffma2(acc[0][2], xp0, wp2); ffma2(acc[0][3], xp0, wp3);
        ffma2(acc[1][0], xp1, wp0); ffma2(acc[1][1], xp1, wp1);
        ffma2(acc[1][2], xp1, wp2); ffma2(acc[1][3], xp1, wp3);
        ffma2(acc[2][0], xp2, wp0); ffma2(acc[2][1], xp2, wp1);
        ffma2(acc[2][2], xp2, wp2); ffma2(acc[2][3], xp2, wp3);
        ffma2(acc[3][0], xp3, wp0); ffma2(acc[3][1], xp3, wp1);
        ffma2(acc[3][2], xp3, wp2); ffma2(acc[3][3], xp3, wp3);
    }

    #pragma unroll
    for (int rp = 0; rp < 4; rp++) {
        int r_even = row0 + r0 + 2 * rp;
        int r_odd  = r_even + 1;
        if (r_even < n) {
            float dv = dinv[r_even];
            float4 o;
            o.x = __uint_as_float((unsigned)(acc[rp][0])) * dv;
            o.y = __uint_as_float((unsigned)(acc[rp][1])) * dv;
            o.z = __uint_as_float((unsigned)(acc[rp][2])) * dv;
            o.w = __uint_as_float((unsigned)(acc[rp][3])) * dv;
            *(float4*)(HS + (size_t)r_even * DH + c0) = o;
        }
        if (r_odd < n) {
            float dv = dinv[r_odd];
            float4 o;
            o.x = __uint_as_float((unsigned)(acc[rp][0] >> 32)) * dv;
            o.y = __uint_as_float((unsigned)(acc[rp][1] >> 32)) * dv;
            o.z = __uint_as_float((unsigned)(acc[rp][2] >> 32)) * dv;
            o.w = __uint_as_float((unsigned)(acc[rp][3] >> 32)) * dv;
            *(float4*)(HS + (size_t)r_odd * DH + c0) = o;
        }
    }
}

// ------- gather + self-loop + dinv + BN + ReLU + residual (fused) -------
// warp per node; lane handles columns [lane*4, lane*4+4)
__global__ __launch_bounds__(256)
void k_gather(const float* __restrict__ HS,
              const int* __restrict__ rowstart, const int* __restrict__ csrc,
              const float* __restrict__ dinv, const float* __restrict__ prev,
              float* __restrict__ Xout,
              const float* __restrict__ cb, const float* __restrict__ gg,
              const float* __restrict__ bt, const float* __restrict__ mm,
              const float* __restrict__ vv)
{
    int warp = (blockIdx.x * blockDim.x + threadIdx.x) >> 5;
    int lane = threadIdx.x & 31;
    if (warp >= N_NODES) return;
    int i = warp;
    int c = lane * 4;

    int s0 = rowstart[i], s1 = rowstart[i + 1];

    // self-loop contribution
    float4 acc = *(const float4*)(HS + (size_t)i * DH + c);

    for (int jb = s0; jb < s1; jb += 32) {
        int idx = 0;
        if (jb + lane < s1) idx = csrc[jb + lane];        // coalesced batch
        int cnt = s1 - jb; if (cnt > 32) cnt = 32;
        for (int q = 0; q < cnt; q++) {
            int s = __shfl_sync(0xffffffffu, idx, q);
            float4 h = *(const float4*)(HS + (size_t)s * DH + c);
            acc.x += h.x; acc.y += h.y; acc.z += h.z; acc.w += h.w;
        }
    }

    float dv = dinv[i];
    float4 cb4 = *(const float4*)(cb + c);
    float4 g4  = *(const float4*)(gg + c);
    float4 bt4 = *(const float4*)(bt + c);
    float4 m4  = *(const float4*)(mm + c);
    float4 v4  = *(const float4*)(vv + c);
    float4 o;
    o.x = fmaxf((acc.x * dv + cb4.x - m4.x) * (g4.x * rsqrtf(v4.x + BN_EPS)) + bt4.x, 0.f);
    o.y = fmaxf((acc.y * dv + cb4.y - m4.y) * (g4.y * rsqrtf(v4.y + BN_EPS)) + bt4.y, 0.f);
    o.z = fmaxf((acc.z * dv + cb4.z - m4.z) * (g4.z * rsqrtf(v4.z + BN_EPS)) + bt4.z, 0.f);
    o.w = fmaxf((acc.w * dv + cb4.w - m4.w) * (g4.w * rsqrtf(v4.w + BN_EPS)) + bt4.w, 0.f);
    if (prev) {
        float4 p = *(const float4*)(prev + (size_t)i * DH + c);
        o.x += p.x; o.y += p.y; o.z += p.z; o.w += p.w;
    }
    *(float4*)(Xout + (size_t)i * DH + c) = o;
}

// ---------------- pooling bounds from sorted batch ----------------
__global__ void k_bounds(const int* __restrict__ batch) {
    int i = blockIdx.x * blockDim.x + threadIdx.x;
    if (i >= N_NODES) return;
    int b = batch[i];
    if (i == 0) {
        for (int q = 0; q <= b; q++) g_gstart[q] = 0;
    } else {
        int pb = batch[i - 1];
        if (b != pb)
            for (int q = pb + 1; q <= b; q++) g_gstart[q] = i;
    }
    if (i == N_NODES - 1)
        for (int q = b + 1; q <= NG; q++) g_gstart[q] = N_NODES;
}

// ---------------- mean+max pooling: one block per graph ----------------
__global__ __launch_bounds__(128)
void k_pool(const float* __restrict__ X) {
    int g = blockIdx.x;
    int c = threadIdx.x;
    int s = g_gstart[g], e = g_gstart[g + 1];
    float sum = 0.f, mx = -INFINITY;
    for (int i = s; i < e; i++) {
        float t = X[(size_t)i * DH + c];
        sum += t;
        mx = fmaxf(mx, t);
    }
    float cnt = (float)(e - s);
    g_pool[g * 2 * DH + c]      = sum / cnt;
    g_pool[g * 2 * DH + DH + c] = mx;
}

// ---------------- MLP head: one block per graph ----------------
__global__ __launch_bounds__(128)
void k_mlp(const float* __restrict__ L1w, const float* __restrict__ L1b,
           const float* __restrict__ L2w, const float* __restrict__ L2b,
           const float* __restrict__ L3w, const float* __restrict__ L3b,
           float* __restrict__ out)
{
    __shared__ float h0[256], h1[128], h2[64];
    int g = blockIdx.x, t = threadIdx.x;
    h0[t]       = g_pool[g * 256 + t];
    h0[t + 128] = g_pool[g * 256 + 128 + t];
    __syncthreads();
    float a = L1b[t];
    #pragma unroll 8
    for (int k = 0; k < 256; k++) a += h0[k] * L1w[k * 128 + t];
    h1[t] = fmaxf(a, 0.f);
    __syncthreads();
    if (t < 64) {
        float b = L2b[t];
        #pragma unroll 8
        for (int k = 0; k < 128; k++) b += h1[k] * L2w[k * 64 + t];
        h2[t] = fmaxf(b, 0.f);
    }
    __syncthreads();
    if (t < 32) {
        float r = h2[t] * L3w[t] + h2[t + 32] * L3w[t + 32];
        #pragma unroll
        for (int off = 16; off; off >>= 1)
            r += __shfl_down_sync(0xffffffffu, r, off);
        if (t == 0) out[g] = r + L3b[0];
    }
}

// ---------------- launch ----------------
extern "C" void kernel_launch(void* const* d_in, const int* in_sizes, int n_in,
                              void* d_out, int out_size)
{
    const float* x    = (const float*)d_in[0];
    const int*   ei   = (const int*)d_in[1];     // int32 (JAX x64 disabled)
    const int*   batc = (const int*)d_in[2];
    const int*   src  = ei;
    const int*   dst  = ei + NE;

    const float* W[3]  = {(const float*)d_in[3],  (const float*)d_in[9],  (const float*)d_in[15]};
    const float* cb[3] = {(const float*)d_in[4],  (const float*)d_in[10], (const float*)d_in[16]};
    const float* gg[3] = {(const float*)d_in[5],  (const float*)d_in[11], (const float*)d_in[17]};
    const float* bt[3] = {(const float*)d_in[6],  (const float*)d_in[12], (const float*)d_in[18]};
    const float* mm[3] = {(const float*)d_in[7],  (const float*)d_in[13], (const float*)d_in[19]};
    const float* vv[3] = {(const float*)d_in[8],  (const float*)d_in[14], (const float*)d_in[20]};
    const float* L1w = (const float*)d_in[21];
    const float* L1b = (const float*)d_in[22];
    const float* L2w = (const float*)d_in[23];
    const float* L2b = (const float*)d_in[24];
    const float* L3w = (const float*)d_in[25];
    const float* L3b = (const float*)d_in[26];
    float* out = (float*)d_out;

    int *pCnt, *pRow, *pCur, *pCsrc, *pCS, *pCB;
    float *pDinv, *pHS, *pXA, *pXB;
    cudaGetSymbolAddress((void**)&pCnt,  g_cnt);
    cudaGetSymbolAddress((void**)&pRow,  g_rowstart);
    cudaGetSymbolAddress((void**)&pCur,  g_cursor);
    cudaGetSymbolAddress((void**)&pCsrc, g_csrc);
    cudaGetSymbolAddress((void**)&pCS,   g_chunksum);
    cudaGetSymbolAddress((void**)&pCB,   g_chunkbase);
    cudaGetSymbolAddress((void**)&pDinv, g_dinv);
    cudaGetSymbolAddress((void**)&pHS,   g_HS);
    cudaGetSymbolAddress((void**)&pXA,   g_XA);
    cudaGetSymbolAddress((void**)&pXB,   g_XB);

    const int smem_gemm = (DH * DH + DH * TR) * (int)sizeof(float);  // 96KB
    cudaFuncSetAttribute(k_gemm, cudaFuncAttributeMaxDynamicSharedMemorySize, smem_gemm);

    // ---- CSR build (per launch, deterministic work) ----
    k_cnt_zero <<<(N_NODES + 255) / 256, 256>>>(pCnt);
    k_deg_count<<<(NE + 255) / 256, 256>>>(dst, pCnt);
    k_dinv     <<<(N_NODES + 255) / 256, 256>>>(pCnt, pDinv);
    k_chunksum <<<8, 128>>>(pCnt, pCS);
    k_chunkscan<<<1, NCHUNK>>>(pCS, pCB);
    k_rowwrite <<<8, 128>>>(pCnt, pCB, pRow, pCur);
    k_fill     <<<(NE + 255) / 256, 256>>>(src, dst, pCur, pCsrc);

    int gemm_blocks = (N_NODES + TR - 1) / TR;
    int gath_blocks = (N_NODES + 7) / 8;   // warp per node, 8 warps/block

    const float* Xin[3]  = {x,   pXA, pXB};
    const float* Prev[3] = {0,   pXA, pXB};
    float*       Xout[3] = {pXA, pXB, pXA};

    for (int L = 0; L < 3; L++) {
        k_gemm<<<gemm_blocks, 256, smem_gemm>>>(Xin[L], W[L], pDinv, pHS, N_NODES);
        k_gather<<<gath_blocks, 256>>>(pHS, pRow, pCsrc, pDinv, Prev[L], Xout[L],
                                       cb[L], gg[L], bt[L], mm[L], vv[L]);
    }

    k_bounds<<<(N_NODES + 255) / 256, 256>>>(batc);
    k_pool<<<NG, 128>>>(pXA);
    k_mlp<<<NG, 128>>>(L1w, L1b, L2w, L2b, L3w, L3b, out);
}

// round 8
// speedup vs baseline: 1.4403x; 1.1842x over previous
#include <cuda_runtime.h>
#include <math.h>

#define N_NODES 100000
#define NE      1600000
#define NG      512
#define DH      128
#define BN_EPS  1e-5f

// ---------------- device scratch (no allocation allowed) ----------------
__device__ int   g_cnt     [N_NODES];
__device__ int   g_rowstart[N_NODES + 1];
__device__ int   g_cursor  [N_NODES];
__device__ int   g_csrc    [NE];
__device__ float g_dinv    [N_NODES];
__device__ float g_HS      [(size_t)N_NODES * DH];
__device__ float g_XA      [(size_t)N_NODES * DH];
__device__ float g_XB      [(size_t)N_NODES * DH];
__device__ float g_pool    [NG * 2 * DH];
__device__ int   g_gstart  [NG + 1];
__device__ int   g_chunksum[1024];
__device__ int   g_chunkbase[1024];

// ---------------- degree / dinv ----------------
__global__ void k_cnt_zero(int* cnt) {
    int i = blockIdx.x * blockDim.x + threadIdx.x;
    if (i < N_NODES) cnt[i] = 0;
}
__global__ void k_deg_count(const int* __restrict__ dst, int* cnt) {
    int e = blockIdx.x * blockDim.x + threadIdx.x;
    if (e < NE) atomicAdd(&cnt[dst[e]], 1);
}
__global__ void k_dinv(const int* __restrict__ cnt, float* __restrict__ dinv) {
    int i = blockIdx.x * blockDim.x + threadIdx.x;
    if (i < N_NODES) dinv[i] = rsqrtf((float)(cnt[i] + 1));  // +1 self-loop
}

// ---------------- distributed 3-phase prefix scan over counts ----------------
#define NCHUNK   1024
#define CHUNK_SZ 98     // 1024*98 = 100352 >= N_NODES

__global__ void k_chunksum(const int* __restrict__ cnt, int* __restrict__ csum) {
    int t = blockIdx.x * blockDim.x + threadIdx.x;
    int lo = t * CHUNK_SZ;
    int hi = lo + CHUNK_SZ; if (hi > N_NODES) hi = N_NODES;
    int s = 0;
    for (int i = lo; i < hi; i++) s += cnt[i];
    csum[t] = s;
}

__global__ __launch_bounds__(NCHUNK)
void k_chunkscan(const int* __restrict__ csum, int* __restrict__ cbase) {
    __shared__ int sums[NCHUNK];
    int t = threadIdx.x;
    int v = csum[t];
    sums[t] = v;
    __syncthreads();
    for (int off = 1; off < NCHUNK; off <<= 1) {
        int u = (t >= off) ? sums[t - off] : 0;
        __syncthreads();
        sums[t] += u;
        __syncthreads();
    }
    cbase[t] = sums[t] - v;   // exclusive
}

__global__ void k_rowwrite(const int* __restrict__ cnt,
                           const int* __restrict__ cbase,
                           int* __restrict__ rowstart, int* __restrict__ cursor)
{
    int t = blockIdx.x * blockDim.x + threadIdx.x;
    int lo = t * CHUNK_SZ;
    int hi = lo + CHUNK_SZ; if (hi > N_NODES) hi = N_NODES;
    int run = cbase[t];
    for (int i = lo; i < hi; i++) {
        rowstart[i] = run;
        cursor[i]   = run;
        run += cnt[i];
    }
    if (t == NCHUNK - 1) rowstart[N_NODES] = run;    // == NE
}

// ---------------- CSR fill ----------------
__global__ void k_fill(const int* __restrict__ src,
                       const int* __restrict__ dst,
                       int* __restrict__ cursor, int* __restrict__ csrc)
{
    int e = blockIdx.x * blockDim.x + threadIdx.x;
    if (e >= NE) return;
    int d = dst[e];
    int pos = atomicAdd(&cursor[d], 1);
    csrc[pos] = src[e];
}

// ---------------- tf32 tensor-core GEMM: HS = (X @ W) * dinv[row] --------
// CTA tile: 128 rows x 128 cols x K=128. 8 warps = 4(m) x 2(n).
// Per warp: M=32 (2 x m16), N=64 (8 x n8), k-loop 16 steps of k8.
#define TM    128          // rows per block
#define SMS   132          // smem row stride (floats) — conflict-free frags

__device__ __forceinline__ unsigned f2tf32(float f) {
    unsigned r;
    asm("cvt.rna.tf32.f32 %0, %1;" : "=r"(r) : "f"(f));
    return r;
}

__global__ __launch_bounds__(256)
void k_gemm(const float* __restrict__ X, const float* __restrict__ W,
            const float* __restrict__ dinv, float* __restrict__ HS, int n)
{
    extern __shared__ unsigned sm[];
    unsigned* Xs = sm;                 // [128][SMS] tf32
    unsigned* Ws = sm + TM * SMS;      // [128][SMS] tf32
    int tid  = threadIdx.x;
    int wid  = tid >> 5;
    int lane = tid & 31;
    int row0 = blockIdx.x * TM;

    // ---- stage X tile (convert to tf32), 128x128, 16 float4 per thread ----
    {
        for (int i = 0; i < 16; i++) {
            int idx = tid + i * 256;          // 0..4095 float4 slots
            int r   = idx >> 5;               // /32 (32 float4 per row)
            int c4  = (idx & 31) << 2;
            int gr  = row0 + r;
            float4 v = make_float4(0.f, 0.f, 0.f, 0.f);
            if (gr < n) v = *(const float4*)(X + (size_t)gr * DH + c4);
            unsigned* p = Xs + r * SMS + c4;
            p[0] = f2tf32(v.x); p[1] = f2tf32(v.y);
            p[2] = f2tf32(v.z); p[3] = f2tf32(v.w);
        }
        for (int i = 0; i < 16; i++) {
            int idx = tid + i * 256;
            int r   = idx >> 5;
            int c4  = (idx & 31) << 2;
            float4 v = *(const float4*)(W + (size_t)r * DH + c4);
            unsigned* p = Ws + r * SMS + c4;
            p[0] = f2tf32(v.x); p[1] = f2tf32(v.y);
            p[2] = f2tf32(v.z); p[3] = f2tf32(v.w);
        }
    }
    __syncthreads();

    int warp_m = wid & 3;          // 0..3 (32 rows each)
    int warp_n = wid >> 2;         // 0..1 (64 cols each)
    int m_base = warp_m * 32;
    int n_base = warp_n * 64;
    int lq = lane >> 2;            // 0..7
    int lr = lane & 3;             // 0..3

    float acc[2][8][4];
    #pragma unroll
    for (int mt = 0; mt < 2; mt++)
        #pragma unroll
        for (int nt = 0; nt < 8; nt++)
            #pragma unroll
            for (int q = 0; q < 4; q++) acc[mt][nt][q] = 0.f;

    const unsigned* Arow = Xs + (m_base + lq) * SMS + lr;   // a0 base
    const unsigned* Brow = Ws + lr * SMS + n_base + lq;     // b0 base

    #pragma unroll
    for (int kk = 0; kk < 16; kk++) {
        int kb = kk * 8;
        unsigned a[2][4];
        #pragma unroll
        for (int mt = 0; mt < 2; mt++) {
            const unsigned* ap = Arow + mt * 16 * SMS + kb;
            a[mt][0] = ap[0];
            a[mt][1] = ap[8 * SMS];
            a[mt][2] = ap[4];
            a[mt][3] = ap[8 * SMS + 4];
        }
        #pragma unroll
        for (int nt = 0; nt < 8; nt++) {
            const unsigned* bp = Brow + (size_t)kb * SMS + nt * 8;
            unsigned b0 = bp[0];
            unsigned b1 = bp[4 * SMS];
            #pragma unroll
            for (int mt = 0; mt < 2; mt++) {
                asm volatile(
                    "mma.sync.aligned.m16n8k8.row.col.f32.tf32.tf32.f32 "
                    "{%0,%1,%2,%3}, {%4,%5,%6,%7}, {%8,%9}, {%0,%1,%2,%3};"
                    : "+f"(acc[mt][nt][0]), "+f"(acc[mt][nt][1]),
                      "+f"(acc[mt][nt][2]), "+f"(acc[mt][nt][3])
                    : "r"(a[mt][0]), "r"(a[mt][1]), "r"(a[mt][2]), "r"(a[mt][3]),
                      "r"(b0), "r"(b1));
            }
        }
    }

    // ---- epilogue: scale by dinv[row], store ----
    #pragma unroll
    for (int mt = 0; mt < 2; mt++) {
        int rA = row0 + m_base + mt * 16 + lq;      // rows for c0,c1
        int rB = rA + 8;                             // rows for c2,c3
        float dvA = (rA < n) ? dinv[rA] : 0.f;
        float dvB = (rB < n) ? dinv[rB] : 0.f;
        #pragma unroll
        for (int nt = 0; nt < 8; nt++) {
            int col = n_base + nt * 8 + lr * 2;
            if (rA < n) {
                float2 o = make_float2(acc[mt][nt][0] * dvA, acc[mt][nt][1] * dvA);
                *(float2*)(HS + (size_t)rA * DH + col) = o;
            }
            if (rB < n) {
                float2 o = make_float2(acc[mt][nt][2] * dvB, acc[mt][nt][3] * dvB);
                *(float2*)(HS + (size_t)rB * DH + col) = o;
            }
        }
    }
}

// ------- gather + self-loop + dinv + BN + ReLU + residual (fused) -------
__global__ __launch_bounds__(256)
void k_gather(const float* __restrict__ HS,
              const int* __restrict__ rowstart, const int* __restrict__ csrc,
              const float* __restrict__ dinv, const float* __restrict__ prev,
              float* __restrict__ Xout,
              const float* __restrict__ cb, const float* __restrict__ gg,
              const float* __restrict__ bt, const float* __restrict__ mm,
              const float* __restrict__ vv)
{
    int warp = (blockIdx.x * blockDim.x + threadIdx.x) >> 5;
    int lane = threadIdx.x & 31;
    if (warp >= N_NODES) return;
    int i = warp;
    int c = lane * 4;

    int s0 = rowstart[i], s1 = rowstart[i + 1];

    float4 acc = *(const float4*)(HS + (size_t)i * DH + c);   // self-loop

    for (int jb = s0; jb < s1; jb += 32) {
        int idx = 0;
        if (jb + lane < s1) idx = csrc[jb + lane];
        int cnt = s1 - jb; if (cnt > 32) cnt = 32;
        for (int q = 0; q < cnt; q++) {
            int s = __shfl_sync(0xffffffffu, idx, q);
            float4 h = *(const float4*)(HS + (size_t)s * DH + c);
            acc.x += h.x; acc.y += h.y; acc.z += h.z; acc.w += h.w;
        }
    }

    float dv = dinv[i];
    float4 cb4 = *(const float4*)(cb + c);
    float4 g4  = *(const float4*)(gg + c);
    float4 bt4 = *(const float4*)(bt + c);
    float4 m4  = *(const float4*)(mm + c);
    float4 v4  = *(const float4*)(vv + c);
    float4 o;
    o.x = fmaxf((acc.x * dv + cb4.x - m4.x) * (g4.x * rsqrtf(v4.x + BN_EPS)) + bt4.x, 0.f);
    o.y = fmaxf((acc.y * dv + cb4.y - m4.y) * (g4.y * rsqrtf(v4.y + BN_EPS)) + bt4.y, 0.f);
    o.z = fmaxf((acc.z * dv + cb4.z - m4.z) * (g4.z * rsqrtf(v4.z + BN_EPS)) + bt4.z, 0.f);
    o.w = fmaxf((acc.w * dv + cb4.w - m4.w) * (g4.w * rsqrtf(v4.w + BN_EPS)) + bt4.w, 0.f);
    if (prev) {
        float4 p = *(const float4*)(prev + (size_t)i * DH + c);
        o.x += p.x; o.y += p.y; o.z += p.z; o.w += p.w;
    }
    *(float4*)(Xout + (size_t)i * DH + c) = o;
}

// ---------------- pooling bounds from sorted batch ----------------
__global__ void k_bounds(const int* __restrict__ batch) {
    int i = blockIdx.x * blockDim.x + threadIdx.x;
    if (i >= N_NODES) return;
    int b = batch[i];
    if (i == 0) {
        for (int q = 0; q <= b; q++) g_gstart[q] = 0;
    } else {
        int pb = batch[i - 1];
        if (b != pb)
            for (int q = pb + 1; q <= b; q++) g_gstart[q] = i;
    }
    if (i == N_NODES - 1)
        for (int q = b + 1; q <= NG; q++) g_gstart[q] = N_NODES;
}

// ---------------- mean+max pooling: one block per graph ----------------
__global__ __launch_bounds__(128)
void k_pool(const float* __restrict__ X) {
    int g = blockIdx.x;
    int c = threadIdx.x;
    int s = g_gstart[g], e = g_gstart[g + 1];
    float sum = 0.f, mx = -INFINITY;
    for (int i = s; i < e; i++) {
        float t = X[(size_t)i * DH + c];
        sum += t;
        mx = fmaxf(mx, t);
    }
    float cnt = (float)(e - s);
    g_pool[g * 2 * DH + c]      = sum / cnt;
    g_pool[g * 2 * DH + DH + c] = mx;
}

// ---------------- MLP head: one block per graph ----------------
__global__ __launch_bounds__(128)
void k_mlp(const float* __restrict__ L1w, const float* __restrict__ L1b,
           const float* __restrict__ L2w, const float* __restrict__ L2b,
           const float* __restrict__ L3w, const float* __restrict__ L3b,
           float* __restrict__ out)
{
    __shared__ float h0[256], h1[128], h2[64];
    int g = blockIdx.x, t = threadIdx.x;
    h0[t]       = g_pool[g * 256 + t];
    h0[t + 128] = g_pool[g * 256 + 128 + t];
    __syncthreads();
    float a = L1b[t];
    #pragma unroll 8
    for (int k = 0; k < 256; k++) a += h0[k] * L1w[k * 128 + t];
    h1[t] = fmaxf(a, 0.f);
    __syncthreads();
    if (t < 64) {
        float b = L2b[t];
        #pragma unroll 8
        for (int k = 0; k < 128; k++) b += h1[k] * L2w[k * 64 + t];
        h2[t] = fmaxf(b, 0.f);
    }
    __syncthreads();
    if (t < 32) {
        float r = h2[t] * L3w[t] + h2[t + 32] * L3w[t + 32];
        #pragma unroll
        for (int off = 16; off; off >>= 1)
            r += __shfl_down_sync(0xffffffffu, r, off);
        if (t == 0) out[g] = r + L3b[0];
    }
}

// ---------------- launch ----------------
extern "C" void kernel_launch(void* const* d_in, const int* in_sizes, int n_in,
                              void* d_out, int out_size)
{
    const float* x    = (const float*)d_in[0];
    const int*   ei   = (const int*)d_in[1];     // int32 (JAX x64 disabled)
    const int*   batc = (const int*)d_in[2];
    const int*   src  = ei;
    const int*   dst  = ei + NE;

    const float* W[3]  = {(const float*)d_in[3],  (const float*)d_in[9],  (const float*)d_in[15]};
    const float* cb[3] = {(const float*)d_in[4],  (const float*)d_in[10], (const float*)d_in[16]};
    const float* gg[3] = {(const float*)d_in[5],  (const float*)d_in[11], (const float*)d_in[17]};
    const float* bt[3] = {(const float*)d_in[6],  (const float*)d_in[12], (const float*)d_in[18]};
    const float* mm[3] = {(const float*)d_in[7],  (const float*)d_in[13], (const float*)d_in[19]};
    const float* vv[3] = {(const float*)d_in[8],  (const float*)d_in[14], (const float*)d_in[20]};
    const float* L1w = (const float*)d_in[21];
    const float* L1b = (const float*)d_in[22];
    const float* L2w = (const float*)d_in[23];
    const float* L2b = (const float*)d_in[24];
    const float* L3w = (const float*)d_in[25];
    const float* L3b = (const float*)d_in[26];
    float* out = (float*)d_out;

    int *pCnt, *pRow, *pCur, *pCsrc, *pCS, *pCB;
    float *pDinv, *pHS, *pXA, *pXB;
    cudaGetSymbolAddress((void**)&pCnt,  g_cnt);
    cudaGetSymbolAddress((void**)&pRow,  g_rowstart);
    cudaGetSymbolAddress((void**)&pCur,  g_cursor);
    cudaGetSymbolAddress((void**)&pCsrc, g_csrc);
    cudaGetSymbolAddress((void**)&pCS,   g_chunksum);
    cudaGetSymbolAddress((void**)&pCB,   g_chunkbase);
    cudaGetSymbolAddress((void**)&pDinv, g_dinv);
    cudaGetSymbolAddress((void**)&pHS,   g_HS);
    cudaGetSymbolAddress((void**)&pXA,   g_XA);
    cudaGetSymbolAddress((void**)&pXB,   g_XB);

    const int smem_gemm = 2 * TM * SMS * (int)sizeof(unsigned);  // 2*128*132*4 = 135168
    cudaFuncSetAttribute(k_gemm, cudaFuncAttributeMaxDynamicSharedMemorySize, smem_gemm);

    // ---- CSR build (per launch, deterministic work) ----
    k_cnt_zero <<<(N_NODES + 255) / 256, 256>>>(pCnt);
    k_deg_count<<<(NE + 255) / 256, 256>>>(dst, pCnt);
    k_dinv     <<<(N_NODES + 255) / 256, 256>>>(pCnt, pDinv);
    k_chunksum <<<8, 128>>>(pCnt, pCS);
    k_chunkscan<<<1, NCHUNK>>>(pCS, pCB);
    k_rowwrite <<<8, 128>>>(pCnt, pCB, pRow, pCur);
    k_fill     <<<(NE + 255) / 256, 256>>>(src, dst, pCur, pCsrc);

    int gemm_blocks = (N_NODES + TM - 1) / TM;
    int gath_blocks = (N_NODES + 7) / 8;   // warp per node, 8 warps/block

    const float* Xin[3]  = {x,   pXA, pXB};
    const float* Prev[3] = {0,   pXA, pXB};
    float*       Xout[3] = {pXA, pXB, pXA};

    for (int L = 0; L < 3; L++) {
        k_gemm<<<gemm_blocks, 256, smem_gemm>>>(Xin[L], W[L], pDinv, pHS, N_NODES);
        k_gather<<<gath_blocks, 256>>>(pHS, pRow, pCsrc, pDinv, Prev[L], Xout[L],
                                       cb[L], gg[L], bt[L], mm[L], vv[L]);
    }

    k_bounds<<<(N_NODES + 255) / 256, 256>>>(batc);
    k_pool<<<NG, 128>>>(pXA);
    k_mlp<<<NG, 128>>>(L1w, L1b, L2w, L2b, L3w, L3b, out);
}

// round 11
// speedup vs baseline: 1.7590x; 1.2213x over previous
#include <cuda_runtime.h>
#include <cuda_fp16.h>
#include <math.h>

#define N_NODES 100000
#define NE      1600000
#define NG      512
#define DH      128
#define BN_EPS  1e-5f

// ---------------- device scratch (no allocation allowed) ----------------
__device__ int    g_cnt     [N_NODES];
__device__ int    g_rowstart[N_NODES + 1];
__device__ int    g_cursor  [N_NODES];
__device__ int    g_csrc    [NE];
__device__ float  g_dinv    [N_NODES];
__device__ __half g_HSh     [(size_t)N_NODES * DH];   // fp16 GEMM output
__device__ float  g_XA      [(size_t)N_NODES * DH];
__device__ float  g_XB      [(size_t)N_NODES * DH];
__device__ float  g_pool    [NG * 2 * DH];
__device__ int    g_gstart  [NG + 1];
__device__ int    g_chunksum[1024];
__device__ int    g_chunkbase[1024];

// ---------------- degree / dinv ----------------
__global__ void k_cnt_zero(int* cnt) {
    int i = blockIdx.x * blockDim.x + threadIdx.x;
    if (i < N_NODES) cnt[i] = 0;
}
__global__ void k_deg_count(const int* __restrict__ dst, int* cnt) {
    int e = blockIdx.x * blockDim.x + threadIdx.x;
    if (e < NE) atomicAdd(&cnt[dst[e]], 1);
}
__global__ void k_dinv(const int* __restrict__ cnt, float* __restrict__ dinv) {
    int i = blockIdx.x * blockDim.x + threadIdx.x;
    if (i < N_NODES) dinv[i] = rsqrtf((float)(cnt[i] + 1));  // +1 self-loop
}

// ---------------- distributed 3-phase prefix scan over counts ----------------
#define NCHUNK   1024
#define CHUNK_SZ 98     // 1024*98 = 100352 >= N_NODES

__global__ void k_chunksum(const int* __restrict__ cnt, int* __restrict__ csum) {
    int t = blockIdx.x * blockDim.x + threadIdx.x;
    int lo = t * CHUNK_SZ;
    int hi = lo + CHUNK_SZ; if (hi > N_NODES) hi = N_NODES;
    int s = 0;
    for (int i = lo; i < hi; i++) s += cnt[i];
    csum[t] = s;
}

__global__ __launch_bounds__(NCHUNK)
void k_chunkscan(const int* __restrict__ csum, int* __restrict__ cbase) {
    __shared__ int sums[NCHUNK];
    int t = threadIdx.x;
    int v = csum[t];
    sums[t] = v;
    __syncthreads();
    for (int off = 1; off < NCHUNK; off <<= 1) {
        int u = (t >= off) ? sums[t - off] : 0;
        __syncthreads();
        sums[t] += u;
        __syncthreads();
    }
    cbase[t] = sums[t] - v;   // exclusive
}

__global__ void k_rowwrite(const int* __restrict__ cnt,
                           const int* __restrict__ cbase,
                           int* __restrict__ rowstart, int* __restrict__ cursor)
{
    int t = blockIdx.x * blockDim.x + threadIdx.x;
    int lo = t * CHUNK_SZ;
    int hi = lo + CHUNK_SZ; if (hi > N_NODES) hi = N_NODES;
    int run = cbase[t];
    for (int i = lo; i < hi; i++) {
        rowstart[i] = run;
        cursor[i]   = run;
        run += cnt[i];
    }
    if (t == NCHUNK - 1) rowstart[N_NODES] = run;    // == NE
}

// ---------------- CSR fill ----------------
__global__ void k_fill(const int* __restrict__ src,
                       const int* __restrict__ dst,
                       int* __restrict__ cursor, int* __restrict__ csrc)
{
    int e = blockIdx.x * blockDim.x + threadIdx.x;
    if (e >= NE) return;
    int d = dst[e];
    int pos = atomicAdd(&cursor[d], 1);
    csrc[pos] = src[e];
}

// ---------------- tf32 tensor-core GEMM: HSh = fp16((X @ W) * dinv[row]) ---
#define TM    128          // rows per block
#define SMS   132          // smem row stride (floats) — conflict-free frags

__device__ __forceinline__ unsigned f2tf32(float f) {
    unsigned r;
    asm("cvt.rna.tf32.f32 %0, %1;" : "=r"(r) : "f"(f));
    return r;
}

__global__ __launch_bounds__(256)
void k_gemm(const float* __restrict__ X, const float* __restrict__ W,
            const float* __restrict__ dinv, __half* __restrict__ HSh, int n)
{
    extern __shared__ unsigned sm[];
    unsigned* Xs = sm;                 // [128][SMS] tf32
    unsigned* Ws = sm + TM * SMS;      // [128][SMS] tf32
    int tid  = threadIdx.x;
    int wid  = tid >> 5;
    int lane = tid & 31;
    int row0 = blockIdx.x * TM;

    {
        for (int i = 0; i < 16; i++) {
            int idx = tid + i * 256;
            int r   = idx >> 5;
            int c4  = (idx & 31) << 2;
            int gr  = row0 + r;
            float4 v = make_float4(0.f, 0.f, 0.f, 0.f);
            if (gr < n) v = *(const float4*)(X + (size_t)gr * DH + c4);
            unsigned* p = Xs + r * SMS + c4;
            p[0] = f2tf32(v.x); p[1] = f2tf32(v.y);
            p[2] = f2tf32(v.z); p[3] = f2tf32(v.w);
        }
        for (int i = 0; i < 16; i++) {
            int idx = tid + i * 256;
            int r   = idx >> 5;
            int c4  = (idx & 31) << 2;
            float4 v = *(const float4*)(W + (size_t)r * DH + c4);
            unsigned* p = Ws + r * SMS + c4;
            p[0] = f2tf32(v.x); p[1] = f2tf32(v.y);
            p[2] = f2tf32(v.z); p[3] = f2tf32(v.w);
        }
    }
    __syncthreads();

    int warp_m = wid & 3;
    int warp_n = wid >> 2;
    int m_base = warp_m * 32;
    int n_base = warp_n * 64;
    int lq = lane >> 2;
    int lr = lane & 3;

    float acc[2][8][4];
    #pragma unroll
    for (int mt = 0; mt < 2; mt++)
        #pragma unroll
        for (int nt = 0; nt < 8; nt++)
            #pragma unroll
            for (int q = 0; q < 4; q++) acc[mt][nt][q] = 0.f;

    const unsigned* Arow = Xs + (m_base + lq) * SMS + lr;
    const unsigned* Brow = Ws + lr * SMS + n_base + lq;

    #pragma unroll
    for (int kk = 0; kk < 16; kk++) {
        int kb = kk * 8;
        unsigned a[2][4];
        #pragma unroll
        for (int mt = 0; mt < 2; mt++) {
            const unsigned* ap = Arow + mt * 16 * SMS + kb;
            a[mt][0] = ap[0];
            a[mt][1] = ap[8 * SMS];
            a[mt][2] = ap[4];
            a[mt][3] = ap[8 * SMS + 4];
        }
        #pragma unroll
        for (int nt = 0; nt < 8; nt++) {
            const unsigned* bp = Brow + (size_t)kb * SMS + nt * 8;
            unsigned b0 = bp[0];
            unsigned b1 = bp[4 * SMS];
            #pragma unroll
            for (int mt = 0; mt < 2; mt++) {
                asm volatile(
                    "mma.sync.aligned.m16n8k8.row.col.f32.tf32.tf32.f32 "
                    "{%0,%1,%2,%3}, {%4,%5,%6,%7}, {%8,%9}, {%0,%1,%2,%3};"
                    : "+f"(acc[mt][nt][0]), "+f"(acc[mt][nt][1]),
                      "+f"(acc[mt][nt][2]), "+f"(acc[mt][nt][3])
                    : "r"(a[mt][0]), "r"(a[mt][1]), "r"(a[mt][2]), "r"(a[mt][3]),
                      "r"(b0), "r"(b1));
            }
        }
    }

    // ---- epilogue: scale by dinv[row], store fp16 ----
    #pragma unroll
    for (int mt = 0; mt < 2; mt++) {
        int rA = row0 + m_base + mt * 16 + lq;
        int rB = rA + 8;
        float dvA = (rA < n) ? dinv[rA] : 0.f;
        float dvB = (rB < n) ? dinv[rB] : 0.f;
        #pragma unroll
        for (int nt = 0; nt < 8; nt++) {
            int col = n_base + nt * 8 + lr * 2;
            if (rA < n) {
                __half2 h = __floats2half2_rn(acc[mt][nt][0] * dvA,
                                              acc[mt][nt][1] * dvA);
                *(__half2*)(HSh + (size_t)rA * DH + col) = h;
            }
            if (rB < n) {
                __half2 h = __floats2half2_rn(acc[mt][nt][2] * dvB,
                                              acc[mt][nt][3] * dvB);
                *(__half2*)(HSh + (size_t)rB * DH + col) = h;
            }
        }
    }
}

// ------- gather(fp16 HS) + self-loop + BN + ReLU + residual (fused) -------
__global__ __launch_bounds__(256)
void k_gather(const __half* __restrict__ HSh,
              const int* __restrict__ rowstart, const int* __restrict__ csrc,
              const float* __restrict__ dinv, const float* __restrict__ prev,
              float* __restrict__ Xout,
              const float* __restrict__ cb, const float* __restrict__ gg,
              const float* __restrict__ bt, const float* __restrict__ mm,
              const float* __restrict__ vv)
{
    int warp = (blockIdx.x * blockDim.x + threadIdx.x) >> 5;
    int lane = threadIdx.x & 31;
    if (warp >= N_NODES) return;
    int i = warp;
    int c = lane * 4;

    int s0 = rowstart[i], s1 = rowstart[i + 1];

    float4 acc;
    {   // self-loop
        uint2 u = *(const uint2*)(HSh + (size_t)i * DH + c);
        float2 f0 = __half22float2(*(__half2*)&u.x);
        float2 f1 = __half22float2(*(__half2*)&u.y);
        acc.x = f0.x; acc.y = f0.y; acc.z = f1.x; acc.w = f1.y;
    }

    for (int jb = s0; jb < s1; jb += 32) {
        int idx = 0;
        if (jb + lane < s1) idx = csrc[jb + lane];
        int cnt = s1 - jb; if (cnt > 32) cnt = 32;
        for (int q = 0; q < cnt; q++) {
            int s = __shfl_sync(0xffffffffu, idx, q);
            uint2 u = *(const uint2*)(HSh + (size_t)s * DH + c);
            float2 f0 = __half22float2(*(__half2*)&u.x);
            float2 f1 = __half22float2(*(__half2*)&u.y);
            acc.x += f0.x; acc.y += f0.y; acc.z += f1.x; acc.w += f1.y;
        }
    }

    float dv = dinv[i];
    float4 cb4 = *(const float4*)(cb + c);
    float4 g4  = *(const float4*)(gg + c);
    float4 bt4 = *(const float4*)(bt + c);
    float4 m4  = *(const float4*)(mm + c);
    float4 v4  = *(const float4*)(vv + c);
    float4 o;
    o.x = fmaxf((acc.x * dv + cb4.x - m4.x) * (g4.x * rsqrtf(v4.x + BN_EPS)) + bt4.x, 0.f);
    o.y = fmaxf((acc.y * dv + cb4.y - m4.y) * (g4.y * rsqrtf(v4.y + BN_EPS)) + bt4.y, 0.f);
    o.z = fmaxf((acc.z * dv + cb4.z - m4.z) * (g4.z * rsqrtf(v4.z + BN_EPS)) + bt4.z, 0.f);
    o.w = fmaxf((acc.w * dv + cb4.w - m4.w) * (g4.w * rsqrtf(v4.w + BN_EPS)) + bt4.w, 0.f);
    if (prev) {
        float4 p = *(const float4*)(prev + (size_t)i * DH + c);
        o.x += p.x; o.y += p.y; o.z += p.z; o.w += p.w;
    }
    *(float4*)(Xout + (size_t)i * DH + c) = o;
}

// ---------------- pooling bounds from sorted batch ----------------
__global__ void k_bounds(const int* __restrict__ batch) {
    int i = blockIdx.x * blockDim.x + threadIdx.x;
    if (i >= N_NODES) return;
    int b = batch[i];
    if (i == 0) {
        for (int q = 0; q <= b; q++) g_gstart[q] = 0;
    } else {
        int pb = batch[i - 1];
        if (b != pb)
            for (int q = pb + 1; q <= b; q++) g_gstart[q] = i;
    }
    if (i == N_NODES - 1)
        for (int q = b + 1; q <= NG; q++) g_gstart[q] = N_NODES;
}

// ---------------- mean+max pooling: one block per graph ----------------
__global__ __launch_bounds__(128)
void k_pool(const float* __restrict__ X) {
    int g = blockIdx.x;
    int c = threadIdx.x;
    int s = g_gstart[g], e = g_gstart[g + 1];
    float sum = 0.f, mx = -INFINITY;
    for (int i = s; i < e; i++) {
        float t = X[(size_t)i * DH + c];
        sum += t;
        mx = fmaxf(mx, t);
    }
    float cnt = (float)(e - s);
    g_pool[g * 2 * DH + c]      = sum / cnt;
    g_pool[g * 2 * DH + DH + c] = mx;
}

// ---------------- MLP head: one block per graph ----------------
__global__ __launch_bounds__(128)
void k_mlp(const float* __restrict__ L1w, const float* __restrict__ L1b,
           const float* __restrict__ L2w, const float* __restrict__ L2b,
           const float* __restrict__ L3w, const float* __restrict__ L3b,
           float* __restrict__ out)
{
    __shared__ float h0[256], h1[128], h2[64];
    int g = blockIdx.x, t = threadIdx.x;
    h0[t]       = g_pool[g * 256 + t];
    h0[t + 128] = g_pool[g * 256 + 128 + t];
    __syncthreads();
    float a = L1b[t];
    #pragma unroll 8
    for (int k = 0; k < 256; k++) a += h0[k] * L1w[k * 128 + t];
    h1[t] = fmaxf(a, 0.f);
    __syncthreads();
    if (t < 64) {
        float b = L2b[t];
        #pragma unroll 8
        for (int k = 0; k < 128; k++) b += h1[k] * L2w[k * 64 + t];
        h2[t] = fmaxf(b, 0.f);
    }
    __syncthreads();
    if (t < 32) {
        float r = h2[t] * L3w[t] + h2[t + 32] * L3w[t + 32];
        #pragma unroll
        for (int off = 16; off; off >>= 1)
            r += __shfl_down_sync(0xffffffffu, r, off);
        if (t == 0) out[g] = r + L3b[0];
    }
}

// ---------------- launch ----------------
extern "C" void kernel_launch(void* const* d_in, const int* in_sizes, int n_in,
                              void* d_out, int out_size)
{
    const float* x    = (const float*)d_in[0];
    const int*   ei   = (const int*)d_in[1];     // int32 (JAX x64 disabled)
    const int*   batc = (const int*)d_in[2];
    const int*   src  = ei;
    const int*   dst  = ei + NE;

    const float* W[3]  = {(const float*)d_in[3],  (const float*)d_in[9],  (const float*)d_in[15]};
    const float* cb[3] = {(const float*)d_in[4],  (const float*)d_in[10], (const float*)d_in[16]};
    const float* gg[3] = {(const float*)d_in[5],  (const float*)d_in[11], (const float*)d_in[17]};
    const float* bt[3] = {(const float*)d_in[6],  (const float*)d_in[12], (const float*)d_in[18]};
    const float* mm[3] = {(const float*)d_in[7],  (const float*)d_in[13], (const float*)d_in[19]};
    const float* vv[3] = {(const float*)d_in[8],  (const float*)d_in[14], (const float*)d_in[20]};
    const float* L1w = (const float*)d_in[21];
    const float* L1b = (const float*)d_in[22];
    const float* L2w = (const float*)d_in[23];
    const float* L2b = (const float*)d_in[24];
    const float* L3w = (const float*)d_in[25];
    const float* L3b = (const float*)d_in[26];
    float* out = (float*)d_out;

    int *pCnt, *pRow, *pCur, *pCsrc, *pCS, *pCB;
    float *pDinv, *pXA, *pXB;
    __half* pHSh;
    cudaGetSymbolAddress((void**)&pCnt,  g_cnt);
    cudaGetSymbolAddress((void**)&pRow,  g_rowstart);
    cudaGetSymbolAddress((void**)&pCur,  g_cursor);
    cudaGetSymbolAddress((void**)&pCsrc, g_csrc);
    cudaGetSymbolAddress((void**)&pCS,   g_chunksum);
    cudaGetSymbolAddress((void**)&pCB,   g_chunkbase);
    cudaGetSymbolAddress((void**)&pDinv, g_dinv);
    cudaGetSymbolAddress((void**)&pHSh,  g_HSh);
    cudaGetSymbolAddress((void**)&pXA,   g_XA);
    cudaGetSymbolAddress((void**)&pXB,   g_XB);

    const int smem_gemm = 2 * TM * SMS * (int)sizeof(unsigned);  // 135168
    cudaFuncSetAttribute(k_gemm, cudaFuncAttributeMaxDynamicSharedMemorySize, smem_gemm);

    // ---- CSR build (per launch, deterministic work) ----
    k_cnt_zero <<<(N_NODES + 255) / 256, 256>>>(pCnt);
    k_deg_count<<<(NE + 255) / 256, 256>>>(dst, pCnt);
    k_dinv     <<<(N_NODES + 255) / 256, 256>>>(pCnt, pDinv);
    k_chunksum <<<8, 128>>>(pCnt, pCS);
    k_chunkscan<<<1, NCHUNK>>>(pCS, pCB);
    k_rowwrite <<<8, 128>>>(pCnt, pCB, pRow, pCur);
    k_fill     <<<(NE + 255) / 256, 256>>>(src, dst, pCur, pCsrc);

    int gemm_blocks = (N_NODES + TM - 1) / TM;
    int gath_blocks = (N_NODES + 7) / 8;   // warp per node, 8 warps/block

    const float* Xin[3]  = {x,   pXA, pXB};
    const float* Prev[3] = {0,   pXA, pXB};
    float*       Xout[3] = {pXA, pXB, pXA};

    for (int L = 0; L < 3; L++) {
        k_gemm<<<gemm_blocks, 256, smem_gemm>>>(Xin[L], W[L], pDinv, pHSh, N_NODES);
        k_gather<<<gath_blocks, 256>>>(pHSh, pRow, pCsrc, pDinv, Prev[L], Xout[L],
                                       cb[L], gg[L], bt[L], mm[L], vv[L]);
    }

    k_bounds<<<(N_NODES + 255) / 256, 256>>>(batc);
    k_pool<<<NG, 128>>>(pXA);
    k_mlp<<<NG, 128>>>(L1w, L1b, L2w, L2b, L3w, L3b, out);
}

// round 16
// speedup vs baseline: 1.8961x; 1.0779x over previous
#include <cuda_runtime.h>
#include <cuda_fp16.h>
#include <math.h>

#define N_NODES 100000
#define NE      1600000
#define NG      512
#define DH      128
#define BN_EPS  1e-5f

// ---------------- device scratch (no allocation allowed) ----------------
__device__ int    g_cnt     [N_NODES];
__device__ int    g_rowstart[N_NODES + 1];
__device__ int    g_cursor  [N_NODES];
__device__ int    g_csrc    [NE];
__device__ float  g_dinv    [N_NODES];
__device__ __half g_HSh     [(size_t)N_NODES * DH];   // fp16 GEMM output
__device__ __half g_XA      [(size_t)N_NODES * DH];   // fp16 activations
__device__ __half g_XB      [(size_t)N_NODES * DH];
__device__ float  g_pool    [NG * 2 * DH];
__device__ int    g_gstart  [NG + 1];
__device__ int    g_chunksum[1024];
__device__ int    g_chunkbase[1024];

// ---------------- degree / dinv ----------------
__global__ void k_cnt_zero(int* cnt) {
    int i = blockIdx.x * blockDim.x + threadIdx.x;
    if (i < N_NODES) cnt[i] = 0;
}
__global__ void k_deg_count(const int2* __restrict__ dst2, int* cnt) {
    int e = blockIdx.x * blockDim.x + threadIdx.x;
    if (e < NE / 2) {
        int2 d = dst2[e];
        atomicAdd(&cnt[d.x], 1);
        atomicAdd(&cnt[d.y], 1);
    }
}
__global__ void k_dinv(const int* __restrict__ cnt, float* __restrict__ dinv) {
    int i = blockIdx.x * blockDim.x + threadIdx.x;
    if (i < N_NODES) dinv[i] = rsqrtf((float)(cnt[i] + 1));  // +1 self-loop
}

// ---------------- distributed 3-phase prefix scan over counts ----------------
#define NCHUNK   1024
#define CHUNK_SZ 98     // 1024*98 = 100352 >= N_NODES

__global__ void k_chunksum(const int* __restrict__ cnt, int* __restrict__ csum) {
    int t = blockIdx.x * blockDim.x + threadIdx.x;
    int lo = t * CHUNK_SZ;
    int hi = lo + CHUNK_SZ; if (hi > N_NODES) hi = N_NODES;
    int s = 0;
    for (int i = lo; i < hi; i++) s += cnt[i];
    csum[t] = s;
}

__global__ __launch_bounds__(NCHUNK)
void k_chunkscan(const int* __restrict__ csum, int* __restrict__ cbase) {
    __shared__ int sums[NCHUNK];
    int t = threadIdx.x;
    int v = csum[t];
    sums[t] = v;
    __syncthreads();
    for (int off = 1; off < NCHUNK; off <<= 1) {
        int u = (t >= off) ? sums[t - off] : 0;
        __syncthreads();
        sums[t] += u;
        __syncthreads();
    }
    cbase[t] = sums[t] - v;   // exclusive
}

__global__ void k_rowwrite(const int* __restrict__ cnt,
                           const int* __restrict__ cbase,
                           int* __restrict__ rowstart, int* __restrict__ cursor)
{
    int t = blockIdx.x * blockDim.x + threadIdx.x;
    int lo = t * CHUNK_SZ;
    int hi = lo + CHUNK_SZ; if (hi > N_NODES) hi = N_NODES;
    int run = cbase[t];
    for (int i = lo; i < hi; i++) {
        rowstart[i] = run;
        cursor[i]   = run;
        run += cnt[i];
    }
    if (t == NCHUNK - 1) rowstart[N_NODES] = run;    // == NE
}

// ---------------- CSR fill (2 edges per thread) ----------------
__global__ void k_fill(const int2* __restrict__ src2,
                       const int2* __restrict__ dst2,
                       int* __restrict__ cursor, int* __restrict__ csrc)
{
    int e = blockIdx.x * blockDim.x + threadIdx.x;
    if (e >= NE / 2) return;
    int2 s = src2[e];
    int2 d = dst2[e];
    int p0 = atomicAdd(&cursor[d.x], 1);
    csrc[p0] = s.x;
    int p1 = atomicAdd(&cursor[d.y], 1);
    csrc[p1] = s.y;
}

// ---------------- tf32 tensor-core GEMM: HSh = fp16((X @ W) * dinv[row]) ---
// Input X is fp32 (layer 0) or fp16 (layers 1,2), selected by in_half.
#define TM    128          // rows per block
#define SMS   132          // smem row stride (floats) — conflict-free frags

__device__ __forceinline__ unsigned f2tf32(float f) {
    unsigned r;
    asm("cvt.rna.tf32.f32 %0, %1;" : "=r"(r) : "f"(f));
    return r;
}

__global__ __launch_bounds__(256)
void k_gemm(const void* __restrict__ Xv, int in_half,
            const float* __restrict__ W,
            const float* __restrict__ dinv, __half* __restrict__ HSh, int n)
{
    extern __shared__ unsigned sm[];
    unsigned* Xs = sm;                 // [128][SMS] tf32
    unsigned* Ws = sm + TM * SMS;      // [128][SMS] tf32
    int tid  = threadIdx.x;
    int wid  = tid >> 5;
    int lane = tid & 31;
    int row0 = blockIdx.x * TM;

    if (in_half) {
        const __half* Xh = (const __half*)Xv;
        for (int i = 0; i < 8; i++) {
            int idx = tid + i * 256;          // 0..2047 uint4 slots
            int r   = idx >> 4;               // 16 uint4 per row
            int c8  = (idx & 15) << 3;        // 8 halfs
            int gr  = row0 + r;
            uint4 u = make_uint4(0, 0, 0, 0);
            if (gr < n) u = *(const uint4*)(Xh + (size_t)gr * DH + c8);
            unsigned* p = Xs + r * SMS + c8;
            float2 f;
            f = __half22float2(*(__half2*)&u.x); p[0] = f2tf32(f.x); p[1] = f2tf32(f.y);
            f = __half22float2(*(__half2*)&u.y); p[2] = f2tf32(f.x); p[3] = f2tf32(f.y);
            f = __half22float2(*(__half2*)&u.z); p[4] = f2tf32(f.x); p[5] = f2tf32(f.y);
            f = __half22float2(*(__half2*)&u.w); p[6] = f2tf32(f.x); p[7] = f2tf32(f.y);
        }
    } else {
        const float* X = (const float*)Xv;
        for (int i = 0; i < 16; i++) {
            int idx = tid + i * 256;          // 0..4095 float4 slots
            int r   = idx >> 5;               // 32 float4 per row
            int c4  = (idx & 31) << 2;
            int gr  = row0 + r;
            float4 v = make_float4(0.f, 0.f, 0.f, 0.f);
            if (gr < n) v = *(const float4*)(X + (size_t)gr * DH + c4);
            unsigned* p = Xs + r * SMS + c4;
            p[0] = f2tf32(v.x); p[1] = f2tf32(v.y);
            p[2] = f2tf32(v.z); p[3] = f2tf32(v.w);
        }
    }
    for (int i = 0; i < 16; i++) {
        int idx = tid + i * 256;
        int r   = idx >> 5;
        int c4  = (idx & 31) << 2;
        float4 v = *(const float4*)(W + (size_t)r * DH + c4);
        unsigned* p = Ws + r * SMS + c4;
        p[0] = f2tf32(v.x); p[1] = f2tf32(v.y);
        p[2] = f2tf32(v.z); p[3] = f2tf32(v.w);
    }
    __syncthreads();

    int warp_m = wid & 3;
    int warp_n = wid >> 2;
    int m_base = warp_m * 32;
    int n_base = warp_n * 64;
    int lq = lane >> 2;
    int lr = lane & 3;

    float acc[2][8][4];
    #pragma unroll
    for (int mt = 0; mt < 2; mt++)
        #pragma unroll
        for (int nt = 0; nt < 8; nt++)
            #pragma unroll
            for (int q = 0; q < 4; q++) acc[mt][nt][q] = 0.f;

    const unsigned* Arow = Xs + (m_base + lq) * SMS + lr;
    const unsigned* Brow = Ws + lr * SMS + n_base + lq;

    #pragma unroll
    for (int kk = 0; kk < 16; kk++) {
        int kb = kk * 8;
        unsigned a[2][4];
        #pragma unroll
        for (int mt = 0; mt < 2; mt++) {
            const unsigned* ap = Arow + mt * 16 * SMS + kb;
            a[mt][0] = ap[0];
            a[mt][1] = ap[8 * SMS];
            a[mt][2] = ap[4];
            a[mt][3] = ap[8 * SMS + 4];
        }
        #pragma unroll
        for (int nt = 0; nt < 8; nt++) {
            const unsigned* bp = Brow + (size_t)kb * SMS + nt * 8;
            unsigned b0 = bp[0];
            unsigned b1 = bp[4 * SMS];
            #pragma unroll
            for (int mt = 0; mt < 2; mt++) {
                asm volatile(
                    "mma.sync.aligned.m16n8k8.row.col.f32.tf32.tf32.f32 "
                    "{%0,%1,%2,%3}, {%4,%5,%6,%7}, {%8,%9}, {%0,%1,%2,%3};"
                    : "+f"(acc[mt][nt][0]), "+f"(acc[mt][nt][1]),
                      "+f"(acc[mt][nt][2]), "+f"(acc[mt][nt][3])
                    : "r"(a[mt][0]), "r"(a[mt][1]), "r"(a[mt][2]), "r"(a[mt][3]),
                      "r"(b0), "r"(b1));
            }
        }
    }

    // ---- epilogue: scale by dinv[row], store fp16 ----
    #pragma unroll
    for (int mt = 0; mt < 2; mt++) {
        int rA = row0 + m_base + mt * 16 + lq;
        int rB = rA + 8;
        float dvA = (rA < n) ? dinv[rA] : 0.f;
        float dvB = (rB < n) ? dinv[rB] : 0.f;
        #pragma unroll
        for (int nt = 0; nt < 8; nt++) {
            int col = n_base + nt * 8 + lr * 2;
            if (rA < n) {
                __half2 h = __floats2half2_rn(acc[mt][nt][0] * dvA,
                                              acc[mt][nt][1] * dvA);
                *(__half2*)(HSh + (size_t)rA * DH + col) = h;
            }
            if (rB < n) {
                __half2 h = __floats2half2_rn(acc[mt][nt][2] * dvB,
                                              acc[mt][nt][3] * dvB);
                *(__half2*)(HSh + (size_t)rB * DH + col) = h;
            }
        }
    }
}

// ------- gather(fp16 HS) + self-loop + BN + ReLU + residual (fused) -------
// fp16 activation output; fp16 residual input.
__global__ __launch_bounds__(256)
void k_gather(const __half* __restrict__ HSh,
              const int* __restrict__ rowstart, const int* __restrict__ csrc,
              const float* __restrict__ dinv, const __half* __restrict__ prev,
              __half* __restrict__ Xout,
              const float* __restrict__ cb, const float* __restrict__ gg,
              const float* __restrict__ bt, const float* __restrict__ mm,
              const float* __restrict__ vv)
{
    int warp = (blockIdx.x * blockDim.x + threadIdx.x) >> 5;
    int lane = threadIdx.x & 31;
    if (warp >= N_NODES) return;
    int i = warp;
    int c = lane * 4;

    int s0 = rowstart[i], s1 = rowstart[i + 1];

    float4 acc;
    {   // self-loop
        uint2 u = *(const uint2*)(HSh + (size_t)i * DH + c);
        float2 f0 = __half22float2(*(__half2*)&u.x);
        float2 f1 = __half22float2(*(__half2*)&u.y);
        acc.x = f0.x; acc.y = f0.y; acc.z = f1.x; acc.w = f1.y;
    }

    for (int jb = s0; jb < s1; jb += 32) {
        int idx = 0;
        if (jb + lane < s1) idx = csrc[jb + lane];
        int cnt = s1 - jb; if (cnt > 32) cnt = 32;
        for (int q = 0; q < cnt; q++) {
            int s = __shfl_sync(0xffffffffu, idx, q);
            uint2 u = *(const uint2*)(HSh + (size_t)s * DH + c);
            float2 f0 = __half22float2(*(__half2*)&u.x);
            float2 f1 = __half22float2(*(__half2*)&u.y);
            acc.x += f0.x; acc.y += f0.y; acc.z += f1.x; acc.w += f1.y;
        }
    }

    float dv = dinv[i];
    float4 cb4 = *(const float4*)(cb + c);
    float4 g4  = *(const float4*)(gg + c);
    float4 bt4 = *(const float4*)(bt + c);
    float4 m4  = *(const float4*)(mm + c);
    float4 v4  = *(const float4*)(vv + c);
    float4 o;
    o.x = fmaxf((acc.x * dv + cb4.x - m4.x) * (g4.x * rsqrtf(v4.x + BN_EPS)) + bt4.x, 0.f);
    o.y = fmaxf((acc.y * dv + cb4.y - m4.y) * (g4.y * rsqrtf(v4.y + BN_EPS)) + bt4.y, 0.f);
    o.z = fmaxf((acc.z * dv + cb4.z - m4.z) * (g4.z * rsqrtf(v4.z + BN_EPS)) + bt4.z, 0.f);
    o.w = fmaxf((acc.w * dv + cb4.w - m4.w) * (g4.w * rsqrtf(v4.w + BN_EPS)) + bt4.w, 0.f);
    if (prev) {
        uint2 u = *(const uint2*)(prev + (size_t)i * DH + c);
        float2 p0 = __half22float2(*(__half2*)&u.x);
        float2 p1 = __half22float2(*(__half2*)&u.y);
        o.x += p0.x; o.y += p0.y; o.z += p1.x; o.w += p1.y;
    }
    __half2 h0 = __floats2half2_rn(o.x, o.y);
    __half2 h1 = __floats2half2_rn(o.z, o.w);
    uint2 st;
    st.x = *(unsigned*)&h0;
    st.y = *(unsigned*)&h1;
    *(uint2*)(Xout + (size_t)i * DH + c) = st;
}

// ---------------- pooling bounds from sorted batch ----------------
__global__ void k_bounds(const int* __restrict__ batch) {
    int i = blockIdx.x * blockDim.x + threadIdx.x;
    if (i >= N_NODES) return;
    int b = batch[i];
    if (i == 0) {
        for (int q = 0; q <= b; q++) g_gstart[q] = 0;
    } else {
        int pb = batch[i - 1];
        if (b != pb)
            for (int q = pb + 1; q <= b; q++) g_gstart[q] = i;
    }
    if (i == N_NODES - 1)
        for (int q = b + 1; q <= NG; q++) g_gstart[q] = N_NODES;
}

// ---------------- mean+max pooling: one block per graph (fp16 in) --------
__global__ __launch_bounds__(128)
void k_pool(const __half* __restrict__ X) {
    int g = blockIdx.x;
    int c = threadIdx.x;
    int s = g_gstart[g], e = g_gstart[g + 1];
    float sum = 0.f, mx = -INFINITY;
    for (int i = s; i < e; i++) {
        float t = __half2float(X[(size_t)i * DH + c]);
        sum += t;
        mx = fmaxf(mx, t);
    }
    float cnt = (float)(e - s);
    g_pool[g * 2 * DH + c]      = sum / cnt;
    g_pool[g * 2 * DH + DH + c] = mx;
}

// ---------------- MLP head: one block per graph ----------------
__global__ __launch_bounds__(128)
void k_mlp(const float* __restrict__ L1w, const float* __restrict__ L1b,
           const float* __restrict__ L2w, const float* __restrict__ L2b,
           const float* __restrict__ L3w, const float* __restrict__ L3b,
           float* __restrict__ out)
{
    __shared__ float h0[256], h1[128], h2[64];
    int g = blockIdx.x, t = threadIdx.x;
    h0[t]       = g_pool[g * 256 + t];
    h0[t + 128] = g_pool[g * 256 + 128 + t];
    __syncthreads();
    float a = L1b[t];
    #pragma unroll 8
    for (int k = 0; k < 256; k++) a += h0[k] * L1w[k * 128 + t];
    h1[t] = fmaxf(a, 0.f);
    __syncthreads();
    if (t < 64) {
        float b = L2b[t];
        #pragma unroll 8
        for (int k = 0; k < 128; k++) b += h1[k] * L2w[k * 64 + t];
        h2[t] = fmaxf(b, 0.f);
    }
    __syncthreads();
    if (t < 32) {
        float r = h2[t] * L3w[t] + h2[t + 32] * L3w[t + 32];
        #pragma unroll
        for (int off = 16; off; off >>= 1)
            r += __shfl_down_sync(0xffffffffu, r, off);
        if (t == 0) out[g] = r + L3b[0];
    }
}

// ---------------- launch ----------------
extern "C" void kernel_launch(void* const* d_in, const int* in_sizes, int n_in,
                              void* d_out, int out_size)
{
    const float* x    = (const float*)d_in[0];
    const int*   ei   = (const int*)d_in[1];     // int32 (JAX x64 disabled)
    const int*   batc = (const int*)d_in[2];
    const int2*  src2 = (const int2*)ei;
    const int2*  dst2 = (const int2*)(ei + NE);

    const float* W[3]  = {(const float*)d_in[3],  (const float*)d_in[9],  (const float*)d_in[15]};
    const float* cb[3] = {(const float*)d_in[4],  (const float*)d_in[10], (const float*)d_in[16]};
    const float* gg[3] = {(const float*)d_in[5],  (const float*)d_in[11], (const float*)d_in[17]};
    const float* bt[3] = {(const float*)d_in[6],  (const float*)d_in[12], (const float*)d_in[18]};
    const float* mm[3] = {(const float*)d_in[7],  (const float*)d_in[13], (const float*)d_in[19]};
    const float* vv[3] = {(const float*)d_in[8],  (const float*)d_in[14], (const float*)d_in[20]};
    const float* L1w = (const float*)d_in[21];
    const float* L1b = (const float*)d_in[22];
    const float* L2w = (const float*)d_in[23];
    const float* L2b = (const float*)d_in[24];
    const float* L3w = (const float*)d_in[25];
    const float* L3b = (const float*)d_in[26];
    float* out = (float*)d_out;

    int *pCnt, *pRow, *pCur, *pCsrc, *pCS, *pCB;
    float *pDinv;
    __half *pHSh, *pXA, *pXB;
    cudaGetSymbolAddress((void**)&pCnt,  g_cnt);
    cudaGetSymbolAddress((void**)&pRow,  g_rowstart);
    cudaGetSymbolAddress((void**)&pCur,  g_cursor);
    cudaGetSymbolAddress((void**)&pCsrc, g_csrc);
    cudaGetSymbolAddress((void**)&pCS,   g_chunksum);
    cudaGetSymbolAddress((void**)&pCB,   g_chunkbase);
    cudaGetSymbolAddress((void**)&pDinv, g_dinv);
    cudaGetSymbolAddress((void**)&pHSh,  g_HSh);
    cudaGetSymbolAddress((void**)&pXA,   g_XA);
    cudaGetSymbolAddress((void**)&pXB,   g_XB);

    const int smem_gemm = 2 * TM * SMS * (int)sizeof(unsigned);  // 135168
    cudaFuncSetAttribute(k_gemm, cudaFuncAttributeMaxDynamicSharedMemorySize, smem_gemm);

    // ---- CSR build (per launch, deterministic work) ----
    k_cnt_zero <<<(N_NODES + 255) / 256, 256>>>(pCnt);
    k_deg_count<<<(NE / 2 + 255) / 256, 256>>>(dst2, pCnt);
    k_dinv     <<<(N_NODES + 255) / 256, 256>>>(pCnt, pDinv);
    k_chunksum <<<8, 128>>>(pCnt, pCS);
    k_chunkscan<<<1, NCHUNK>>>(pCS, pCB);
    k_rowwrite <<<8, 128>>>(pCnt, pCB, pRow, pCur);
    k_fill     <<<(NE / 2 + 255) / 256, 256>>>(src2, dst2, pCur, pCsrc);

    int gemm_blocks = (N_NODES + TM - 1) / TM;
    int gath_blocks = (N_NODES + 7) / 8;   // warp per node, 8 warps/block

    const void*   Xin[3]  = {(const void*)x, (const void*)pXA, (const void*)pXB};
    const int     InH[3]  = {0, 1, 1};
    const __half* Prev[3] = {0,   pXA, pXB};
    __half*       Xout[3] = {pXA, pXB, pXA};

    for (int L = 0; L < 3; L++) {
        k_gemm<<<gemm_blocks, 256, smem_gemm>>>(Xin[L], InH[L], W[L], pDinv, pHSh, N_NODES);
        k_gather<<<gath_blocks, 256>>>(pHSh, pRow, pCsrc, pDinv, Prev[L], Xout[L],
                                       cb[L], gg[L], bt[L], mm[L], vv[L]);
    }

    k_bounds<<<(N_NODES + 255) / 256, 256>>>(batc);
    k_pool<<<NG, 128>>>(pXA);
    k_mlp<<<NG, 128>>>(L1w, L1b, L2w, L2b, L3w, L3b, out);
}